// round 4
// baseline (speedup 1.0000x reference)
#include <cuda_runtime.h>
#include <cuda_fp16.h>
#include <mma.h>
#include <stdint.h>

using namespace nvcuda;

#define B_   32
#define S_   512
#define H_   512
#define E_   512
#define G4H  2048
#define BS_  (B_*S_)          // 16384
#define BH_  (B_*H_)          // 16384 elems (h state per dir)

// ---------------- scratch (__device__ globals; no allocation allowed) ----------------
__device__ __half g_X0h[BS_*E_];             // embedded input hi
__device__ __half g_X0l[BS_*E_];             // embedded input lo
__device__ __half g_y0h[BS_*2*H_];           // layer0 output hi [B,S,2H]
__device__ __half g_y0l[BS_*2*H_];
__device__ __half g_y1h[BS_*2*H_];           // layer1 output hi
__device__ __half g_y1l[BS_*2*H_];
__device__ float  g_xp0[(size_t)BS_*G4H];    // input proj fp32, fwd dir
__device__ float  g_xp1[(size_t)BS_*G4H];    // input proj fp32, bwd dir
__device__ __half g_Wih_h[2*2*(size_t)G4H*1024];  // [layer][dir] Wih hi (K up to 1024)
__device__ __half g_Wih_l[2*2*(size_t)G4H*1024];
__device__ __half g_Whh_h[2*2*(size_t)G4H*H_];    // [layer][dir] Whh hi
__device__ __half g_Whh_l[2*2*(size_t)G4H*H_];
__device__ float  g_bsum[2*2*G4H];                // bih+bhh (fp32 exact)
__device__ __half g_hbh[2*2*BH_];            // [parity][dir] h state hi
__device__ __half g_hbl[2*2*BH_];            // [parity][dir] h state lo
__device__ unsigned g_bar_cnt;
__device__ unsigned g_bar_gen;

// ---------------- small utility kernels ----------------
__global__ void k_split(const float* __restrict__ src, __half* __restrict__ dh,
                        __half* __restrict__ dl, int n4) {
    int i = blockIdx.x * blockDim.x + threadIdx.x;
    if (i < n4) {
        float4 v = ((const float4*)src)[i];
        __half h0 = __float2half(v.x), h1 = __float2half(v.y);
        __half h2 = __float2half(v.z), h3 = __float2half(v.w);
        __half2* dhp = (__half2*)(dh + (size_t)i * 4);
        __half2* dlp = (__half2*)(dl + (size_t)i * 4);
        dhp[0] = __halves2half2(h0, h1);
        dhp[1] = __halves2half2(h2, h3);
        dlp[0] = __floats2half2_rn(v.x - __half2float(h0), v.y - __half2float(h1));
        dlp[1] = __floats2half2_rn(v.z - __half2float(h2), v.w - __half2float(h3));
    }
}

__global__ void k_bias_sum(const float* __restrict__ a, const float* __restrict__ b,
                           float* __restrict__ o, int n) {
    int i = blockIdx.x * blockDim.x + threadIdx.x;
    if (i < n) o[i] = a[i] + b[i];
}

__global__ void k_embed(const int* __restrict__ x, const float* __restrict__ emb,
                        __half* __restrict__ oh, __half* __restrict__ ol) {
    int chunk = blockIdx.x * blockDim.x + threadIdx.x;   // over BS_ * (E_/4)
    if (chunk < BS_ * (E_ / 4)) {
        int i = chunk >> 7;
        int j = chunk & 127;
        int tok = x[i];
        float4 v = ((const float4*)emb)[(size_t)tok * (E_ / 4) + j];
        __half h0 = __float2half(v.x), h1 = __float2half(v.y);
        __half h2 = __float2half(v.z), h3 = __float2half(v.w);
        __half2* dh = (__half2*)(oh + (size_t)i * E_ + j * 4);
        __half2* dl = (__half2*)(ol + (size_t)i * E_ + j * 4);
        dh[0] = __halves2half2(h0, h1);
        dh[1] = __halves2half2(h2, h3);
        dl[0] = __floats2half2_rn(v.x - __half2float(h0), v.y - __half2float(h1));
        dl[1] = __floats2half2_rn(v.z - __half2float(h2), v.w - __half2float(h3));
    }
}

// ---------------- split input-projection GEMM: C[M,2048] = A[M,K] * W[2048,K]^T ----------
// 3 passes accumulated in fp32: Ah*Wh + Al*Wh + Ah*Wl
#define GBM 128
#define GBN 128
#define GBK 32
#define GPAD 8

__device__ __forceinline__ void cpasync16(void* s, const void* g) {
    uint32_t sa = (uint32_t)__cvta_generic_to_shared(s);
    asm volatile("cp.async.cg.shared.global [%0], [%1], 16;\n" :: "r"(sa), "l"(g));
}

__global__ __launch_bounds__(256) void k_gemm3(const __half* __restrict__ Ah,
                                               const __half* __restrict__ Al,
                                               const __half* __restrict__ Wh,
                                               const __half* __restrict__ Wl,
                                               float* __restrict__ C, int K) {
    __shared__ __half As[2][GBM][GBK + GPAD];
    __shared__ __half Ws[2][GBN][GBK + GPAD];
    int tid = threadIdx.x;
    int bm = blockIdx.y, bn = blockIdx.x;
    const __half* Ap[3] = {Ah, Al, Ah};
    const __half* Wp[3] = {Wh, Wh, Wl};
    int wid = tid >> 5;
    int wm = wid & 3;
    int wn = wid >> 2;

    wmma::fragment<wmma::accumulator, 16, 16, 16, float> acc[2][4];
    #pragma unroll
    for (int i = 0; i < 2; i++)
        #pragma unroll
        for (int j = 0; j < 4; j++) wmma::fill_fragment(acc[i][j], 0.f);

    int NT = K / GBK;
    int TT = 3 * NT;

    auto load_tile = [&](int tt, int buf) {
        int pass = (tt >= 2 * NT) ? 2 : (tt >= NT ? 1 : 0);
        int kt = tt - pass * NT;
        const __half* Ab = Ap[pass] + (size_t)bm * GBM * K + kt * GBK;
        const __half* Wb = Wp[pass] + (size_t)bn * GBN * K + kt * GBK;
        #pragma unroll
        for (int j = 0; j < 2; j++) {
            int c = tid + j * 256;
            int row = c >> 2, cc = (c & 3) * 8;
            cpasync16(&As[buf][row][cc], Ab + (size_t)row * K + cc);
            cpasync16(&Ws[buf][row][cc], Wb + (size_t)row * K + cc);
        }
        asm volatile("cp.async.commit_group;\n");
    };

    load_tile(0, 0);
    asm volatile("cp.async.wait_group 0;\n");
    __syncthreads();

    for (int tt = 0; tt < TT; tt++) {
        int cur = tt & 1;
        if (tt + 1 < TT) load_tile(tt + 1, cur ^ 1);
        #pragma unroll
        for (int kk = 0; kk < 2; kk++) {
            wmma::fragment<wmma::matrix_a, 16, 16, 16, __half, wmma::row_major> af[2];
            wmma::fragment<wmma::matrix_b, 16, 16, 16, __half, wmma::col_major> bf[4];
            #pragma unroll
            for (int i = 0; i < 2; i++)
                wmma::load_matrix_sync(af[i], &As[cur][wm * 32 + i * 16][kk * 16], GBK + GPAD);
            #pragma unroll
            for (int j = 0; j < 4; j++)
                wmma::load_matrix_sync(bf[j], &Ws[cur][wn * 64 + j * 16][kk * 16], GBK + GPAD);
            #pragma unroll
            for (int i = 0; i < 2; i++)
                #pragma unroll
                for (int j = 0; j < 4; j++)
                    wmma::mma_sync(acc[i][j], af[i], bf[j], acc[i][j]);
        }
        if (tt + 1 < TT) asm volatile("cp.async.wait_group 0;\n");
        __syncthreads();
    }

    #pragma unroll
    for (int i = 0; i < 2; i++)
        #pragma unroll
        for (int j = 0; j < 4; j++) {
            int row = bm * GBM + wm * 32 + i * 16;
            int col = bn * GBN + wn * 64 + j * 16;
            wmma::store_matrix_sync(C + (size_t)row * G4H + col, acc[i][j], G4H,
                                    wmma::mem_row_major);
        }
}

// ---------------- persistent bidirectional LSTM recurrence (split-fp16) ----------------
// 128 CTAs: blocks 0-63 = fwd, 64-127 = bwd. Each CTA owns 8 hidden units
// (= 32 Whh rows: 4 gates x 8 units). Whh_hi fragments live in registers,
// Whh_lo in smem; h state is hi/lo planes double-buffered through L2.
#define RNB 128
#define LDH 520      // 512 + 8 halves pad
#define LDGS 36
#define RECSM (3*32*LDH*2 + 32*LDGS*4)   // Wlo + Hhi + Hlo (fp16) + Gs (fp32) = 104448 B

__device__ __forceinline__ void gridbar(unsigned nblk) {
    __syncthreads();
    if (threadIdx.x == 0) {
        volatile unsigned* vg = &g_bar_gen;
        unsigned gen = *vg;
        __threadfence();
        unsigned t = atomicAdd(&g_bar_cnt, 1);
        if (t == nblk - 1) {
            atomicExch(&g_bar_cnt, 0);
            __threadfence();
            atomicAdd(&g_bar_gen, 1);
        } else {
            while (*vg == gen) { }
        }
        __threadfence();
    }
    __syncthreads();
}

__device__ __forceinline__ float sigmoidf_(float x) { return 1.f / (1.f + __expf(-x)); }
__device__ __forceinline__ float tanhf_(float x) {
    x = fminf(fmaxf(x, -15.f), 15.f);
    float e = __expf(2.f * x);
    return (e - 1.f) / (e + 1.f);
}

__global__ __launch_bounds__(128) void k_rec(const float* __restrict__ xpf,
                                             const float* __restrict__ xpb,
                                             const __half* __restrict__ Whf_h,
                                             const __half* __restrict__ Whf_l,
                                             const __half* __restrict__ Whb_h,
                                             const __half* __restrict__ Whb_l,
                                             const float* __restrict__ bsf,
                                             const float* __restrict__ bsb,
                                             __half* __restrict__ yh,
                                             __half* __restrict__ yl) {
    extern __shared__ char smraw[];
    __half* Wlo = (__half*)smraw;                        // [32][LDH] persistent
    __half* Hhi = (__half*)(smraw + 32 * LDH * 2);       // [32][LDH] (also temp Whi at init)
    __half* Hlo = (__half*)(smraw + 2 * 32 * LDH * 2);   // [32][LDH]
    float*  Gs  = (float*)(smraw + 3 * 32 * LDH * 2);    // [32][LDGS]

    int tid = threadIdx.x;
    int blk = blockIdx.x;
    int dir = blk >> 6;                 // 0 fwd, 1 bwd
    int grp = blk & 63;
    int ub  = grp * 8;                  // first hidden unit owned
    const __half* Wh_h = dir ? Whb_h : Whf_h;
    const __half* Wh_l = dir ? Whb_l : Whf_l;
    const float*  xp   = dir ? xpb : xpf;
    const float*  bs   = dir ? bsb : bsf;

    // Stage Whh_hi rows into Hhi (temp): smem row c = q*8+u -> Whh row q*512+ub+u
    for (int chunk = tid; chunk < 32 * 64; chunk += 128) {
        int c = chunk >> 6, w8 = (chunk & 63) * 8;
        int q = c >> 3, u = c & 7;
        uint4 v = *(const uint4*)(Wh_h + (size_t)(q * H_ + ub + u) * H_ + w8);
        *(uint4*)(Hhi + c * LDH + w8) = v;
    }

    // Per-thread elementwise items: it = tid + 128*j -> (b = it>>3, u = it&7)
    float bias[2][4];
    float cst[2] = {0.f, 0.f};
    #pragma unroll
    for (int j = 0; j < 2; j++) {
        int it = tid + 128 * j;
        int b = it >> 3, u = it & 7;
        #pragma unroll
        for (int q = 0; q < 4; q++) bias[j][q] = bs[q * H_ + ub + u];
        // zero-init h state (parity 0, both planes)
        __stcg((unsigned short*)&g_hbh[(0 * 2 + dir) * BH_ + b * H_ + ub + u], (unsigned short)0);
        __stcg((unsigned short*)&g_hbl[(0 * 2 + dir) * BH_ + b * H_ + ub + u], (unsigned short)0);
    }
    __syncthreads();

    // Preload Whh_hi b-fragments into registers (persistent; 32 frags x 4 regs)
    int wid = tid >> 5;
    int mi = wid & 1;       // batch halves 0-15 / 16-31
    int ni = wid >> 1;      // gate-col halves 0-15 / 16-31
    wmma::fragment<wmma::matrix_b, 16, 16, 16, __half, wmma::col_major> bfr[32];
    #pragma unroll
    for (int kk = 0; kk < 32; kk++)
        wmma::load_matrix_sync(bfr[kk], Hhi + (ni * 16) * LDH + kk * 16, LDH);
    __syncthreads();

    // Load Whh_lo rows into persistent smem
    for (int chunk = tid; chunk < 32 * 64; chunk += 128) {
        int c = chunk >> 6, w8 = (chunk & 63) * 8;
        int q = c >> 3, u = c & 7;
        uint4 v = *(const uint4*)(Wh_l + (size_t)(q * H_ + ub + u) * H_ + w8);
        *(uint4*)(Wlo + c * LDH + w8) = v;
    }

    __threadfence();
    gridbar(RNB);

    for (int s = 0; s < S_; s++) {
        int p = s & 1;
        const __half* hsh = &g_hbh[(p * 2 + dir) * BH_];
        const __half* hsl = &g_hbl[(p * 2 + dir) * BH_];
        for (int chunk = tid; chunk < 32 * 64; chunk += 128) {
            int b = chunk >> 6, w8 = (chunk & 63) * 8;
            uint4 vh = __ldcg((const uint4*)(hsh + b * H_ + w8));
            uint4 vl = __ldcg((const uint4*)(hsl + b * H_ + w8));
            *(uint4*)(Hhi + b * LDH + w8) = vh;
            *(uint4*)(Hlo + b * LDH + w8) = vl;
        }
        __syncthreads();

        wmma::fragment<wmma::accumulator, 16, 16, 16, float> acc;
        wmma::fill_fragment(acc, 0.f);
        #pragma unroll
        for (int kk = 0; kk < 32; kk++) {
            wmma::fragment<wmma::matrix_a, 16, 16, 16, __half, wmma::row_major> ah, al;
            wmma::fragment<wmma::matrix_b, 16, 16, 16, __half, wmma::col_major> bl;
            wmma::load_matrix_sync(ah, Hhi + (mi * 16) * LDH + kk * 16, LDH);
            wmma::load_matrix_sync(al, Hlo + (mi * 16) * LDH + kk * 16, LDH);
            wmma::load_matrix_sync(bl, Wlo + (ni * 16) * LDH + kk * 16, LDH);
            wmma::mma_sync(acc, ah, bfr[kk], acc);   // hi*hi
            wmma::mma_sync(acc, al, bfr[kk], acc);   // lo*hi
            wmma::mma_sync(acc, ah, bl, acc);        // hi*lo
        }
        wmma::store_matrix_sync(Gs + (mi * 16) * LDGS + ni * 16, acc, LDGS, wmma::mem_row_major);
        __syncthreads();

        int t = dir ? (S_ - 1 - s) : s;
        #pragma unroll
        for (int j = 0; j < 2; j++) {
            int it = tid + 128 * j;
            int b = it >> 3, u = it & 7;
            const float* xr = xp + (size_t)(b * S_ + t) * G4H + ub + u;
            float gi = Gs[b * LDGS + u]       + xr[0]    + bias[j][0];
            float gf = Gs[b * LDGS + 8 + u]   + xr[512]  + bias[j][1];
            float gg = Gs[b * LDGS + 16 + u]  + xr[1024] + bias[j][2];
            float go = Gs[b * LDGS + 24 + u]  + xr[1536] + bias[j][3];
            float cc = sigmoidf_(gf) * cst[j] + sigmoidf_(gi) * tanhf_(gg);
            cst[j] = cc;
            float h = sigmoidf_(go) * tanhf_(cc);
            __half hh = __float2half(h);
            __half hl = __float2half(h - __half2float(hh));
            int ho = ((p ^ 1) * 2 + dir) * BH_ + b * H_ + ub + u;
            __stcg((unsigned short*)&g_hbh[ho], __half_as_ushort(hh));
            __stcg((unsigned short*)&g_hbl[ho], __half_as_ushort(hl));
            size_t yo = (size_t)(b * S_ + t) * (2 * H_) + dir * H_ + ub + u;
            yh[yo] = hh;
            yl[yo] = hl;
        }
        __threadfence();
        gridbar(RNB);
    }
}

// ---------------- masked mean-pool + FC (fp32) ----------------
__global__ __launch_bounds__(256) void k_pool(const __half* __restrict__ yh,
                                              const __half* __restrict__ yl,
                                              const int* __restrict__ mask,
                                              const float* __restrict__ fcW,
                                              const float* __restrict__ fcb,
                                              float* __restrict__ out) {
    int b = blockIdx.x, tid = threadIdx.x;
    __shared__ float pooled[1024];
    __shared__ float red[256];
    float acc[4] = {0.f, 0.f, 0.f, 0.f};
    float cnt = 0.f;
    for (int s = 0; s < S_; s++) {
        float m = (float)mask[b * S_ + s];
        cnt += m;
        const __half* yrh = yh + (size_t)(b * S_ + s) * 1024;
        const __half* yrl = yl + (size_t)(b * S_ + s) * 1024;
        #pragma unroll
        for (int j = 0; j < 4; j++) {
            int k = tid + j * 256;
            acc[j] += m * (__half2float(yrh[k]) + __half2float(yrl[k]));
        }
    }
    float inv = 1.f / fmaxf(cnt, 1e-9f);
    #pragma unroll
    for (int j = 0; j < 4; j++) pooled[tid + j * 256] = acc[j] * inv;
    __syncthreads();
    for (int c = 0; c < 2; c++) {
        float p = 0.f;
        #pragma unroll
        for (int j = 0; j < 4; j++) {
            int k = tid + j * 256;
            p += pooled[k] * fcW[c * 1024 + k];
        }
        red[tid] = p;
        __syncthreads();
        for (int st = 128; st > 0; st >>= 1) {
            if (tid < st) red[tid] += red[tid + st];
            __syncthreads();
        }
        if (tid == 0) out[b * 2 + c] = red[0] + fcb[c];
        __syncthreads();
    }
}

// ---------------- host orchestration ----------------
extern "C" void kernel_launch(void* const* d_in, const int* in_sizes, int n_in,
                              void* d_out, int out_size) {
    const int*   x   = (const int*)d_in[0];
    const int*   am  = (const int*)d_in[1];
    const float* emb = (const float*)d_in[2];
    const float* fcW = (const float*)d_in[3];
    const float* fcb = (const float*)d_in[4];
    const float* Wih[2][2] = {{(const float*)d_in[5],  (const float*)d_in[9]},
                              {(const float*)d_in[13], (const float*)d_in[17]}};
    const float* Whh[2][2] = {{(const float*)d_in[6],  (const float*)d_in[10]},
                              {(const float*)d_in[14], (const float*)d_in[18]}};
    const float* bih[2][2] = {{(const float*)d_in[7],  (const float*)d_in[11]},
                              {(const float*)d_in[15], (const float*)d_in[19]}};
    const float* bhh[2][2] = {{(const float*)d_in[8],  (const float*)d_in[12]},
                              {(const float*)d_in[16], (const float*)d_in[20]}};

    void *pX0h, *pX0l, *py0h, *py0l, *py1h, *py1l, *pxp0, *pxp1;
    void *pWihH, *pWihL, *pWhhH, *pWhhL, *pbs;
    cudaGetSymbolAddress(&pX0h, g_X0h);
    cudaGetSymbolAddress(&pX0l, g_X0l);
    cudaGetSymbolAddress(&py0h, g_y0h);
    cudaGetSymbolAddress(&py0l, g_y0l);
    cudaGetSymbolAddress(&py1h, g_y1h);
    cudaGetSymbolAddress(&py1l, g_y1l);
    cudaGetSymbolAddress(&pxp0, g_xp0);
    cudaGetSymbolAddress(&pxp1, g_xp1);
    cudaGetSymbolAddress(&pWihH, g_Wih_h);
    cudaGetSymbolAddress(&pWihL, g_Wih_l);
    cudaGetSymbolAddress(&pWhhH, g_Whh_h);
    cudaGetSymbolAddress(&pWhhL, g_Whh_l);
    cudaGetSymbolAddress(&pbs,  g_bsum);

    cudaFuncSetAttribute(k_rec, cudaFuncAttributeMaxDynamicSharedMemorySize, RECSM);

    const size_t WIH_STRIDE = (size_t)G4H * 1024;
    const size_t WHH_STRIDE = (size_t)G4H * H_;

    // weight split conversions + bias sums
    for (int l = 0; l < 2; l++) {
        int K = (l == 0) ? E_ : 2 * H_;
        for (int d = 0; d < 2; d++) {
            int idx = l * 2 + d;
            int n4w = G4H * K / 4;
            k_split<<<(n4w + 255) / 256, 256>>>(Wih[l][d],
                                                (__half*)pWihH + idx * WIH_STRIDE,
                                                (__half*)pWihL + idx * WIH_STRIDE, n4w);
            int n4h = G4H * H_ / 4;
            k_split<<<(n4h + 255) / 256, 256>>>(Whh[l][d],
                                                (__half*)pWhhH + idx * WHH_STRIDE,
                                                (__half*)pWhhL + idx * WHH_STRIDE, n4h);
            k_bias_sum<<<(G4H + 255) / 256, 256>>>(bih[l][d], bhh[l][d],
                                                   (float*)pbs + idx * G4H, G4H);
        }
    }

    // embedding gather -> split fp16
    k_embed<<<(BS_ * (E_ / 4) + 255) / 256, 256>>>(x, emb, (__half*)pX0h, (__half*)pX0l);

    dim3 ggrid(G4H / GBN, BS_ / GBM);  // (16, 128)

    // ----- layer 0 -----
    k_gemm3<<<ggrid, 256>>>((const __half*)pX0h, (const __half*)pX0l,
                            (const __half*)pWihH + 0 * WIH_STRIDE,
                            (const __half*)pWihL + 0 * WIH_STRIDE, (float*)pxp0, E_);
    k_gemm3<<<ggrid, 256>>>((const __half*)pX0h, (const __half*)pX0l,
                            (const __half*)pWihH + 1 * WIH_STRIDE,
                            (const __half*)pWihL + 1 * WIH_STRIDE, (float*)pxp1, E_);
    k_rec<<<RNB, 128, RECSM>>>((const float*)pxp0, (const float*)pxp1,
                               (const __half*)pWhhH + 0 * WHH_STRIDE,
                               (const __half*)pWhhL + 0 * WHH_STRIDE,
                               (const __half*)pWhhH + 1 * WHH_STRIDE,
                               (const __half*)pWhhL + 1 * WHH_STRIDE,
                               (const float*)pbs + 0 * G4H, (const float*)pbs + 1 * G4H,
                               (__half*)py0h, (__half*)py0l);

    // ----- layer 1 -----
    k_gemm3<<<ggrid, 256>>>((const __half*)py0h, (const __half*)py0l,
                            (const __half*)pWihH + 2 * WIH_STRIDE,
                            (const __half*)pWihL + 2 * WIH_STRIDE, (float*)pxp0, 2 * H_);
    k_gemm3<<<ggrid, 256>>>((const __half*)py0h, (const __half*)py0l,
                            (const __half*)pWihH + 3 * WIH_STRIDE,
                            (const __half*)pWihL + 3 * WIH_STRIDE, (float*)pxp1, 2 * H_);
    k_rec<<<RNB, 128, RECSM>>>((const float*)pxp0, (const float*)pxp1,
                               (const __half*)pWhhH + 2 * WHH_STRIDE,
                               (const __half*)pWhhL + 2 * WHH_STRIDE,
                               (const __half*)pWhhH + 3 * WHH_STRIDE,
                               (const __half*)pWhhL + 3 * WHH_STRIDE,
                               (const float*)pbs + 2 * G4H, (const float*)pbs + 3 * G4H,
                               (__half*)py1h, (__half*)py1l);

    // ----- pool + fc -----
    k_pool<<<B_, 256>>>((const __half*)py1h, (const __half*)py1l, am, fcW, fcb, (float*)d_out);
}